// round 9
// baseline (speedup 1.0000x reference)
#include <cuda_runtime.h>
#include <cuda_bf16.h>
#include <math.h>

#define NH    8
#define EDIM  32
#define WS    8
#define MO    12
#define NKEY  (MO*MO)      // 144
#define NKPAD 160
#define BATCH 16
#define CCH   256
#define HH    64
#define WW    64
#define PIX   (HH*WW)      // 4096
#define NWIN  8

typedef unsigned long long u64;
typedef unsigned int u32;

// bf16 hi/lo split scratch
__device__ __nv_bfloat16 g_xh[BATCH * PIX * CCH];   // x transposed: (b, p, c)
__device__ __nv_bfloat16 g_xl[BATCH * PIX * CCH];
__device__ __nv_bfloat16 g_w1h[768 * CCH];          // (n, k)
__device__ __nv_bfloat16 g_w1l[768 * CCH];
__device__ __nv_bfloat16 g_w2h[CCH * CCH];
__device__ __nv_bfloat16 g_w2l[CCH * CCH];
__device__ __nv_bfloat16 g_Qh[BATCH * NH * PIX * EDIM];  // (b, head, pixel, e)
__device__ __nv_bfloat16 g_Ql[BATCH * NH * PIX * EDIM];
__device__ __nv_bfloat16 g_Kh[BATCH * NH * PIX * EDIM];
__device__ __nv_bfloat16 g_Kl[BATCH * NH * PIX * EDIM];
__device__ __nv_bfloat16 g_Vh[BATCH * NH * PIX * EDIM];
__device__ __nv_bfloat16 g_Vl[BATCH * NH * PIX * EDIM];
__device__ __nv_bfloat16 g_atth[BATCH * PIX * CCH]; // attn out hi (b, p, c)
__device__ __nv_bfloat16 g_attl[BATCH * PIX * CCH]; // attn out lo

// ---- fast exp on FMA pipe ----
__device__ __forceinline__ float fast_exp(float x) {
    float y = fmaxf(x * 1.4426950408889634f, -125.0f);
    float z = y + 12582912.0f;
    int   n = __float_as_int(z) - 0x4B400000;
    float f = y - (z - 12582912.0f);
    float p = 1.540353039338161e-4f;
    p = fmaf(p, f, 0.0013333558146428443f);
    p = fmaf(p, f, 0.009618129107628477f);
    p = fmaf(p, f, 0.05550410866482158f);
    p = fmaf(p, f, 0.2402265069591007f);
    p = fmaf(p, f, 0.6931471805599453f);
    p = fmaf(p, f, 1.0f);
    return p * __int_as_float((n + 127) << 23);
}

// ---- mma.sync helpers ----
__device__ __forceinline__ u32 smem_u32(const void* p) {
    u32 a; asm("{ .reg .u64 t; cvta.to.shared.u64 t, %1; cvt.u32.u64 %0, t; }"
               : "=r"(a) : "l"(p));
    return a;
}
__device__ __forceinline__ void ldsm4(u32* r, u32 addr) {
    asm volatile("ldmatrix.sync.aligned.m8n8.x4.shared.b16 {%0,%1,%2,%3}, [%4];"
                 : "=r"(r[0]), "=r"(r[1]), "=r"(r[2]), "=r"(r[3]) : "r"(addr));
}
__device__ __forceinline__ void mma_bf16(float* d, const u32* a, const u32* b) {
    asm volatile(
        "mma.sync.aligned.m16n8k16.row.col.f32.bf16.bf16.f32 "
        "{%0,%1,%2,%3}, {%4,%5,%6,%7}, {%8,%9}, {%0,%1,%2,%3};"
        : "+f"(d[0]), "+f"(d[1]), "+f"(d[2]), "+f"(d[3])
        : "r"(a[0]), "r"(a[1]), "r"(a[2]), "r"(a[3]), "r"(b[0]), "r"(b[1]));
}
__device__ __forceinline__ void cp16(u32 dst, const void* src) {
    asm volatile("cp.async.cg.shared.global [%0], [%1], 16;"
                 :: "r"(dst), "l"(src));
}
#define CP_COMMIT() asm volatile("cp.async.commit_group;" ::: "memory")
#define CP_WAIT0()  asm volatile("cp.async.wait_group 0;" ::: "memory")

__device__ __forceinline__ void split_bf16(float v, __nv_bfloat16& hi, __nv_bfloat16& lo) {
    hi = __float2bfloat16(v);
    lo = __float2bfloat16(v - __bfloat162float(hi));
}

// GEMM smem
#define KPAD 72
#define TILE_B (128 * KPAD * 2)       // 18432 bytes
#define GEMM_SMEM (4 * TILE_B)        // 73728 bytes

// ---------------------------------------------------------------------------
// Conversion kernels
// ---------------------------------------------------------------------------
__global__ void conv_x(const float* __restrict__ x) {
    __shared__ float tile[32][33];
    const int b  = blockIdx.z;
    const int p0 = blockIdx.x * 32;
    const int c0 = blockIdx.y * 32;
    const int tx = threadIdx.x, ty = threadIdx.y;   // 32 x 8
    const float* xb = x + ((size_t)b * CCH + c0) * PIX + p0;
#pragma unroll
    for (int i = 0; i < 32; i += 8)
        tile[ty + i][tx] = xb[(size_t)(ty + i) * PIX + tx];
    __syncthreads();
#pragma unroll
    for (int i = 0; i < 32; i += 8) {
        int p = p0 + ty + i;
        float v = tile[tx][ty + i];
        __nv_bfloat16 hi, lo; split_bf16(v, hi, lo);
        size_t o = ((size_t)b * PIX + p) * CCH + c0 + tx;
        g_xh[o] = hi;
        g_xl[o] = lo;
    }
}

__global__ void conv_w(const float* __restrict__ w, __nv_bfloat16* __restrict__ wh,
                       __nv_bfloat16* __restrict__ wl, int n) {
    int i = blockIdx.x * 256 + threadIdx.x;
    if (i < n) {
        __nv_bfloat16 hi, lo; split_bf16(w[i], hi, lo);
        wh[i] = hi;
        wl[i] = lo;
    }
}

// ---------------------------------------------------------------------------
// Kernel 1: QKV projection (mma.sync bf16x3 + cp.async, 2 CTAs/SM).
// Epilogue writes Q/K/V as bf16 hi/lo.
// ---------------------------------------------------------------------------
__global__ __launch_bounds__(256, 2) void qkv_mma(const float* __restrict__ b1) {
    extern __shared__ char smem[];
    char* sAh = smem;
    char* sAl = smem + TILE_B;
    char* sBh = smem + 2 * TILE_B;
    char* sBl = smem + 3 * TILE_B;
    const u32 uAh = smem_u32(sAh), uAl = smem_u32(sAl);
    const u32 uBh = smem_u32(sBh), uBl = smem_u32(sBl);

    const int tid = threadIdx.x;
    const int lane = tid & 31, wid = tid >> 5;
    const int warp_m = wid >> 1, warp_n = wid & 1;
    const int b  = blockIdx.z;
    const int p0 = blockIdx.x * 128;
    const int n0 = blockIdx.y * 128;

    const int g = lane >> 3, rr = lane & 7;
    const u32 offA = (u32)(((warp_m * 32 + rr + (g & 1) * 8) * KPAD + (g >> 1) * 8) * 2);
    const u32 offB = (u32)(((warp_n * 64 + (g >> 1) * 8 + rr) * KPAD + (g & 1) * 8) * 2);

    float acc[2][8][4];
#pragma unroll
    for (int ma = 0; ma < 2; ma++)
#pragma unroll
        for (int na = 0; na < 8; na++)
#pragma unroll
            for (int v = 0; v < 4; v++) acc[ma][na][v] = 0.f;

    const __nv_bfloat16* Ah = g_xh + (size_t)b * PIX * CCH;
    const __nv_bfloat16* Al = g_xl + (size_t)b * PIX * CCH;

    for (int c0 = 0; c0 < CCH; c0 += 64) {
#pragma unroll
        for (int t = 0; t < 4; t++) {
            int idx = tid + t * 256;
            int row = idx >> 3, seg = idx & 7;
            size_t srcA = ((size_t)(p0 + row)) * CCH + c0 + seg * 8;
            size_t srcB = ((size_t)(n0 + row)) * CCH + c0 + seg * 8;
            u32 doff = (u32)(row * (KPAD * 2) + seg * 16);
            cp16(uAh + doff, Ah + srcA);
            cp16(uAl + doff, Al + srcA);
            cp16(uBh + doff, g_w1h + srcB);
            cp16(uBl + doff, g_w1l + srcB);
        }
        CP_COMMIT();
        CP_WAIT0();
        __syncthreads();

#pragma unroll
        for (int ks = 0; ks < 4; ks++) {
            const u32 ko = ks * 32;
            u32 ah[2][4], al[2][4];
            ldsm4(ah[0], uAh + offA + ko);
            ldsm4(ah[1], uAh + offA + ko + 16 * KPAD * 2);
            ldsm4(al[0], uAl + offA + ko);
            ldsm4(al[1], uAl + offA + ko + 16 * KPAD * 2);
#pragma unroll
            for (int ng = 0; ng < 4; ng++) {
                u32 bh[4], bl[4];
                ldsm4(bh, uBh + offB + ko + ng * (16 * KPAD * 2));
                ldsm4(bl, uBl + offB + ko + ng * (16 * KPAD * 2));
#pragma unroll
                for (int h = 0; h < 2; h++) {
                    const u32* bhf = bh + 2 * h;
                    const u32* blf = bl + 2 * h;
                    int na = ng * 2 + h;
#pragma unroll
                    for (int ma = 0; ma < 2; ma++) {
                        mma_bf16(acc[ma][na], ah[ma], bhf);
                        mma_bf16(acc[ma][na], ah[ma], blf);
                        mma_bf16(acc[ma][na], al[ma], bhf);
                    }
                }
            }
        }
        __syncthreads();
    }

    // Epilogue: scatter bf16 hi/lo into Q/K/V
    const int r = lane >> 2;
    const int cp = (lane & 3) * 2;
#pragma unroll
    for (int ma = 0; ma < 2; ma++) {
#pragma unroll
        for (int na = 0; na < 8; na++) {
#pragma unroll
            for (int v = 0; v < 4; v++) {
                int m  = p0 + warp_m * 32 + ma * 16 + r + (v >> 1) * 8;
                int oc = n0 + warp_n * 64 + na * 8 + cp + (v & 1);
                float val = acc[ma][na][v] + b1[oc];
                int type = oc % 3;
                int ch   = oc / 3;
                int head = ch >> 5;
                int e    = ch & 31;
                __nv_bfloat16* dh = (type == 0) ? g_Qh : (type == 1) ? g_Kh : g_Vh;
                __nv_bfloat16* dl = (type == 0) ? g_Ql : (type == 1) ? g_Kl : g_Vl;
                __nv_bfloat16 hi, lo; split_bf16(val, hi, lo);
                size_t off = ((size_t)(b * NH + head) * PIX + m) * EDIM + e;
                dh[off] = hi;
                dl[off] = lo;
            }
        }
    }
}

// ---------------------------------------------------------------------------
// Kernel 2: windowed attention via mma.sync bf16x3. One block (128 thr, 4
// warps) per (b, head, window). Warp w owns query rows 16w..16w+15 through
// all phases -> only __syncwarp between phases after the load sync.
// ---------------------------------------------------------------------------
#define AQ_K   40            // Q/K smem k-stride (elements); row = 80 B
#define AVT_S  168           // Vt key-stride (elements); row = 336 B
#define AS_S   172           // S fp32 col-stride; row = 688 B
#define PROW_B (AS_S * 4)    // 688: P overlays S row-locally
#define PLO_B  352           // P_lo byte offset within row (16B aligned)
// smem byte offsets
#define A_QH  0
#define A_QL  5120
#define A_KH  10240
#define A_KL  23040
#define A_VTH 35840
#define A_VTL 46592
#define A_S   57344
#define ATTN_SMEM (A_S + 64 * PROW_B)   // 101376

__global__ __launch_bounds__(128) void attn_mma() {
    extern __shared__ char sm[];
    const u32 sb = smem_u32(sm);

    const int b    = blockIdx.z;
    const int head = blockIdx.y;
    const int wi   = blockIdx.x >> 3;
    const int wj   = blockIdx.x & 7;
    const int tid  = threadIdx.x;
    const int lane = tid & 31;
    const int warp = tid >> 5;

    const size_t hb = (size_t)(b * NH + head) * PIX * EDIM;

    // ---- Load Q (64x32), K (160x32 rows, zero pad), Vt (32x160 cols, zero pad)
    for (int idx = tid; idx < 64 * EDIM; idx += 128) {
        int q = idx >> 5, e = idx & 31;
        int r = wi * 8 + (q >> 3);
        int c = wj * 8 + (q & 7);
        size_t off = hb + (size_t)(r * WW + c) * EDIM + e;
        *(__nv_bfloat16*)(sm + A_QH + (q * AQ_K + e) * 2) = g_Qh[off];
        *(__nv_bfloat16*)(sm + A_QL + (q * AQ_K + e) * 2) = g_Ql[off];
    }
    for (int idx = tid; idx < NKPAD * EDIM; idx += 128) {
        int k = idx >> 5, e = idx & 31;
        __nv_bfloat16 kh = __float2bfloat16(0.f), kl = kh, vh = kh, vl = kh;
        if (k < NKEY) {
            int kr = k / MO, kc = k % MO;
            int r = wi * 8 - 2 + kr;
            int c = wj * 8 - 2 + kc;
            if (r >= 0 && r < HH && c >= 0 && c < WW) {
                size_t off = hb + (size_t)(r * WW + c) * EDIM + e;
                kh = g_Kh[off]; kl = g_Kl[off];
                vh = g_Vh[off]; vl = g_Vl[off];
            }
        }
        *(__nv_bfloat16*)(sm + A_KH + (k * AQ_K + e) * 2) = kh;
        *(__nv_bfloat16*)(sm + A_KL + (k * AQ_K + e) * 2) = kl;
        *(__nv_bfloat16*)(sm + A_VTH + (e * AVT_S + k) * 2) = vh;
        *(__nv_bfloat16*)(sm + A_VTL + (e * AVT_S + k) * 2) = vl;
    }
    __syncthreads();

    const int g = lane >> 3, rr = lane & 7;

    // ---- QK^T: warp m-atom (16 q) x 20 n-atoms (160 keys) x 2 ksteps, bf16x3
    {
        const u32 aoff = (u32)(((warp * 16 + rr + (g & 1) * 8) * AQ_K + (g >> 1) * 8) * 2);
        const u32 boff = (u32)((((g >> 1) * 8 + rr) * AQ_K + (g & 1) * 8) * 2);
        float acc[20][4];
#pragma unroll
        for (int na = 0; na < 20; na++)
#pragma unroll
            for (int v = 0; v < 4; v++) acc[na][v] = 0.f;

#pragma unroll
        for (int ks = 0; ks < 2; ks++) {
            const u32 ko = ks * 32;
            u32 ah[4], al[4];
            ldsm4(ah, sb + A_QH + aoff + ko);
            ldsm4(al, sb + A_QL + aoff + ko);
#pragma unroll
            for (int ng = 0; ng < 10; ng++) {
                u32 bh[4], bl[4];
                const u32 nb = ng * (16 * AQ_K * 2);
                ldsm4(bh, sb + A_KH + boff + nb + ko);
                ldsm4(bl, sb + A_KL + boff + nb + ko);
#pragma unroll
                for (int h = 0; h < 2; h++) {
                    int na = ng * 2 + h;
                    mma_bf16(acc[na], ah, bh + 2 * h);
                    mma_bf16(acc[na], ah, bl + 2 * h);
                    mma_bf16(acc[na], al, bh + 2 * h);
                }
            }
        }
        // store scaled scores to S fp32
        const float scale = 0.17677669529663687f;   // 1/sqrt(32)
        const int r0 = warp * 16 + (lane >> 2);
        const int c0 = (lane & 3) * 2;
#pragma unroll
        for (int na = 0; na < 20; na++) {
            int col = na * 8 + c0;
            *(float2*)(sm + A_S + (size_t)r0 * PROW_B + col * 4) =
                make_float2(acc[na][0] * scale, acc[na][1] * scale);
            *(float2*)(sm + A_S + (size_t)(r0 + 8) * PROW_B + col * 4) =
                make_float2(acc[na][2] * scale, acc[na][3] * scale);
        }
    }
    __syncwarp();

    // ---- softmax over 144 real keys (2 threads/row), register-staged;
    //      write P bf16 hi/lo overlaying the row's own S bytes.
    {
        const int row  = tid >> 1;
        const int half = tid & 1;
        const float* src = (const float*)(sm + A_S + (size_t)row * PROW_B) + half * 72;
        float v[72];
#pragma unroll
        for (int k = 0; k < 72; k++) v[k] = src[k];
        float m = -1e30f;
#pragma unroll
        for (int k = 0; k < 72; k++) m = fmaxf(m, v[k]);
        m = fmaxf(m, __shfl_xor_sync(0xFFFFFFFFu, m, 1));
        float s = 0.f;
#pragma unroll
        for (int k = 0; k < 72; k++) {
            v[k] = fast_exp(v[k] - m);
            s += v[k];
        }
        s += __shfl_xor_sync(0xFFFFFFFFu, s, 1);
        float inv = 1.f / s;
        __syncwarp();   // all reads of S row done before overlay writes
        char* prow = sm + A_S + (size_t)row * PROW_B;
#pragma unroll
        for (int k = 0; k < 72; k++) {
            float p = v[k] * inv;
            __nv_bfloat16 hi, lo; split_bf16(p, hi, lo);
            int col = half * 72 + k;
            *(__nv_bfloat16*)(prow + col * 2) = hi;
            *(__nv_bfloat16*)(prow + PLO_B + col * 2) = lo;
        }
        if (half) {   // zero pad keys 144..159
#pragma unroll
            for (int k = NKEY; k < NKPAD; k++) {
                *(__nv_bfloat16*)(prow + k * 2) = __float2bfloat16(0.f);
                *(__nv_bfloat16*)(prow + PLO_B + k * 2) = __float2bfloat16(0.f);
            }
        }
    }
    __syncwarp();

    // ---- A@V: warp m-atom (16 q) x 4 n-atoms (32 e) x 10 ksteps, bf16x3
    {
        const u32 paoff = (u32)((warp * 16 + rr + (g & 1) * 8) * PROW_B + (g >> 1) * 16);
        const u32 vboff = (u32)((((g >> 1) * 8 + rr) * AVT_S + (g & 1) * 8) * 2);
        float acc[4][4];
#pragma unroll
        for (int na = 0; na < 4; na++)
#pragma unroll
            for (int v = 0; v < 4; v++) acc[na][v] = 0.f;

#pragma unroll
        for (int ks = 0; ks < 10; ks++) {
            const u32 ko = ks * 32;
            u32 ph[4], pl[4];
            ldsm4(ph, sb + A_S + paoff + ko);
            ldsm4(pl, sb + A_S + PLO_B + paoff + ko);
#pragma unroll
            for (int ng = 0; ng < 2; ng++) {
                u32 vh[4], vl[4];
                const u32 nb = ng * (16 * AVT_S * 2);
                ldsm4(vh, sb + A_VTH + vboff + nb + ko);
                ldsm4(vl, sb + A_VTL + vboff + nb + ko);
#pragma unroll
                for (int h = 0; h < 2; h++) {
                    int na = ng * 2 + h;
                    mma_bf16(acc[na], ph, vh + 2 * h);
                    mma_bf16(acc[na], ph, vl + 2 * h);
                    mma_bf16(acc[na], pl, vh + 2 * h);
                }
            }
        }
        // epilogue: write bf16 hi/lo to g_atth/g_attl (b, pixel, head*32+e)
        const int r0 = lane >> 2;
        const int e0 = (lane & 3) * 2;
#pragma unroll
        for (int half = 0; half < 2; half++) {
            int q = warp * 16 + r0 + half * 8;
            int r = wi * 8 + (q >> 3);
            int c = wj * 8 + (q & 7);
            size_t base = ((size_t)b * PIX + r * WW + c) * CCH + head * EDIM;
#pragma unroll
            for (int na = 0; na < 4; na++) {
                int e = na * 8 + e0;
                float o0 = acc[na][half * 2 + 0];
                float o1 = acc[na][half * 2 + 1];
                __nv_bfloat16 h0, l0, h1, l1;
                split_bf16(o0, h0, l0);
                split_bf16(o1, h1, l1);
                __nv_bfloat162 hh; hh.x = h0; hh.y = h1;
                __nv_bfloat162 ll; ll.x = l0; ll.y = l1;
                *(__nv_bfloat162*)(g_atth + base + e) = hh;
                *(__nv_bfloat162*)(g_attl + base + e) = ll;
            }
        }
    }
}

// ---------------------------------------------------------------------------
// Kernel 3: output projection (mma.sync bf16x3 + cp.async, 2 CTAs/SM).
// ---------------------------------------------------------------------------
__global__ __launch_bounds__(256, 2) void proj_mma(const float* __restrict__ b2,
                                                   float* __restrict__ y) {
    extern __shared__ char smem[];
    char* sAh = smem;
    char* sAl = smem + TILE_B;
    char* sBh = smem + 2 * TILE_B;
    char* sBl = smem + 3 * TILE_B;
    const u32 uAh = smem_u32(sAh), uAl = smem_u32(sAl);
    const u32 uBh = smem_u32(sBh), uBl = smem_u32(sBl);

    const int tid = threadIdx.x;
    const int lane = tid & 31, wid = tid >> 5;
    const int warp_m = wid >> 1, warp_n = wid & 1;
    const int b  = blockIdx.z;
    const int p0 = blockIdx.x * 128;
    const int n0 = blockIdx.y * 128;

    const int g = lane >> 3, rr = lane & 7;
    const u32 offA = (u32)(((warp_m * 32 + rr + (g & 1) * 8) * KPAD + (g >> 1) * 8) * 2);
    const u32 offB = (u32)(((warp_n * 64 + (g >> 1) * 8 + rr) * KPAD + (g & 1) * 8) * 2);

    float acc[2][8][4];
#pragma unroll
    for (int ma = 0; ma < 2; ma++)
#pragma unroll
        for (int na = 0; na < 8; na++)
#pragma unroll
            for (int v = 0; v < 4; v++) acc[ma][na][v] = 0.f;

    const __nv_bfloat16* Ah = g_atth + (size_t)b * PIX * CCH;
    const __nv_bfloat16* Al = g_attl + (size_t)b * PIX * CCH;

    for (int c0 = 0; c0 < CCH; c0 += 64) {
#pragma unroll
        for (int t = 0; t < 4; t++) {
            int idx = tid + t * 256;
            int row = idx >> 3, seg = idx & 7;
            size_t srcA = ((size_t)(p0 + row)) * CCH + c0 + seg * 8;
            size_t srcB = ((size_t)(n0 + row)) * CCH + c0 + seg * 8;
            u32 doff = (u32)(row * (KPAD * 2) + seg * 16);
            cp16(uAh + doff, Ah + srcA);
            cp16(uAl + doff, Al + srcA);
            cp16(uBh + doff, g_w2h + srcB);
            cp16(uBl + doff, g_w2l + srcB);
        }
        CP_COMMIT();
        CP_WAIT0();
        __syncthreads();

#pragma unroll
        for (int ks = 0; ks < 4; ks++) {
            const u32 ko = ks * 32;
            u32 ah[2][4], al[2][4];
            ldsm4(ah[0], uAh + offA + ko);
            ldsm4(ah[1], uAh + offA + ko + 16 * KPAD * 2);
            ldsm4(al[0], uAl + offA + ko);
            ldsm4(al[1], uAl + offA + ko + 16 * KPAD * 2);
#pragma unroll
            for (int ng = 0; ng < 4; ng++) {
                u32 bh[4], bl[4];
                ldsm4(bh, uBh + offB + ko + ng * (16 * KPAD * 2));
                ldsm4(bl, uBl + offB + ko + ng * (16 * KPAD * 2));
#pragma unroll
                for (int h = 0; h < 2; h++) {
                    const u32* bhf = bh + 2 * h;
                    const u32* blf = bl + 2 * h;
                    int na = ng * 2 + h;
#pragma unroll
                    for (int ma = 0; ma < 2; ma++) {
                        mma_bf16(acc[ma][na], ah[ma], bhf);
                        mma_bf16(acc[ma][na], ah[ma], blf);
                        mma_bf16(acc[ma][na], al[ma], bhf);
                    }
                }
            }
        }
        __syncthreads();
    }

    // Epilogue: y[b][n][p]
    const int r = lane >> 2;
    const int cp = (lane & 3) * 2;
#pragma unroll
    for (int ma = 0; ma < 2; ma++) {
#pragma unroll
        for (int na = 0; na < 8; na++) {
#pragma unroll
            for (int v = 0; v < 4; v++) {
                int m = p0 + warp_m * 32 + ma * 16 + r + (v >> 1) * 8;
                int n = n0 + warp_n * 64 + na * 8 + cp + (v & 1);
                y[((size_t)(b * CCH + n)) * PIX + m] = acc[ma][na][v] + b2[n];
            }
        }
    }
}

// ---------------------------------------------------------------------------
extern "C" void kernel_launch(void* const* d_in, const int* in_sizes, int n_in,
                              void* d_out, int out_size) {
    const float* x  = (const float*)d_in[0];
    const float* W1 = (const float*)d_in[1];
    const float* b1 = (const float*)d_in[2];
    const float* W2 = (const float*)d_in[3];
    const float* b2 = (const float*)d_in[4];
    float* y = (float*)d_out;

    cudaFuncSetAttribute(attn_mma,
                         cudaFuncAttributeMaxDynamicSharedMemorySize, ATTN_SMEM);
    cudaFuncSetAttribute(qkv_mma,
                         cudaFuncAttributeMaxDynamicSharedMemorySize, GEMM_SMEM);
    cudaFuncSetAttribute(proj_mma,
                         cudaFuncAttributeMaxDynamicSharedMemorySize, GEMM_SMEM);

    __nv_bfloat16 *w1h, *w1l, *w2h, *w2l;
    cudaGetSymbolAddress((void**)&w1h, g_w1h);
    cudaGetSymbolAddress((void**)&w1l, g_w1l);
    cudaGetSymbolAddress((void**)&w2h, g_w2h);
    cudaGetSymbolAddress((void**)&w2l, g_w2l);

    // 0) fp32 -> bf16 hi/lo splits
    conv_x<<<dim3(PIX / 32, CCH / 32, BATCH), dim3(32, 8)>>>(x);
    conv_w<<<(768 * CCH + 255) / 256, 256>>>(W1, w1h, w1l, 768 * CCH);
    conv_w<<<(CCH * CCH + 255) / 256, 256>>>(W2, w2h, w2l, CCH * CCH);

    // 1) QKV: M=4096 (x128), N=768 (x128), per batch
    qkv_mma<<<dim3(PIX / 128, 768 / 128, BATCH), 256, GEMM_SMEM>>>(b1);

    // 2) Attention: (64 windows, 8 heads, 16 batches)
    attn_mma<<<dim3(NWIN * NWIN, NH, BATCH), 128, ATTN_SMEM>>>();

    // 3) Output projection: N=256 (x128)
    proj_mma<<<dim3(PIX / 128, CCH / 128, BATCH), 256, GEMM_SMEM>>>(b2, y);
}

// round 10
// speedup vs baseline: 1.3991x; 1.3991x over previous
#include <cuda_runtime.h>
#include <cuda_bf16.h>
#include <math.h>

#define NH    8
#define EDIM  32
#define WS    8
#define MO    12
#define NKEY  (MO*MO)      // 144
#define BATCH 16
#define CCH   256
#define HH    64
#define WW    64
#define PIX   (HH*WW)      // 4096
#define NWIN  8

typedef unsigned long long u64;
typedef unsigned int u32;

// Scratch buffers
__device__ float g_Q[BATCH * NH * PIX * EDIM];    // (b, head, pixel, e)
__device__ float g_K[BATCH * NH * PIX * EDIM];
__device__ float g_V[BATCH * NH * PIX * EDIM];

// bf16 hi/lo split scratch
__device__ __nv_bfloat16 g_xh[BATCH * PIX * CCH];   // x transposed: (b, p, c)
__device__ __nv_bfloat16 g_xl[BATCH * PIX * CCH];
__device__ __nv_bfloat16 g_w1h[768 * CCH];          // (n, k)
__device__ __nv_bfloat16 g_w1l[768 * CCH];
__device__ __nv_bfloat16 g_w2h[CCH * CCH];
__device__ __nv_bfloat16 g_w2l[CCH * CCH];
__device__ __nv_bfloat16 g_atth[BATCH * PIX * CCH]; // attn out hi (b, p, c)
__device__ __nv_bfloat16 g_attl[BATCH * PIX * CCH]; // attn out lo

// ---- fast exp on FMA pipe ----
__device__ __forceinline__ float fast_exp(float x) {
    float y = fmaxf(x * 1.4426950408889634f, -125.0f);
    float z = y + 12582912.0f;
    int   n = __float_as_int(z) - 0x4B400000;
    float f = y - (z - 12582912.0f);
    float p = 1.540353039338161e-4f;
    p = fmaf(p, f, 0.0013333558146428443f);
    p = fmaf(p, f, 0.009618129107628477f);
    p = fmaf(p, f, 0.05550410866482158f);
    p = fmaf(p, f, 0.2402265069591007f);
    p = fmaf(p, f, 0.6931471805599453f);
    p = fmaf(p, f, 1.0f);
    return p * __int_as_float((n + 127) << 23);
}

// ---- mma.sync helpers ----
__device__ __forceinline__ u32 smem_u32(const void* p) {
    u32 a; asm("{ .reg .u64 t; cvta.to.shared.u64 t, %1; cvt.u32.u64 %0, t; }"
               : "=r"(a) : "l"(p));
    return a;
}
__device__ __forceinline__ void ldsm4(u32* r, u32 addr) {
    asm volatile("ldmatrix.sync.aligned.m8n8.x4.shared.b16 {%0,%1,%2,%3}, [%4];"
                 : "=r"(r[0]), "=r"(r[1]), "=r"(r[2]), "=r"(r[3]) : "r"(addr));
}
__device__ __forceinline__ void mma_bf16(float* d, const u32* a, const u32* b) {
    asm volatile(
        "mma.sync.aligned.m16n8k16.row.col.f32.bf16.bf16.f32 "
        "{%0,%1,%2,%3}, {%4,%5,%6,%7}, {%8,%9}, {%0,%1,%2,%3};"
        : "+f"(d[0]), "+f"(d[1]), "+f"(d[2]), "+f"(d[3])
        : "r"(a[0]), "r"(a[1]), "r"(a[2]), "r"(a[3]), "r"(b[0]), "r"(b[1]));
}
__device__ __forceinline__ void cp16(u32 dst, const void* src) {
    asm volatile("cp.async.cg.shared.global [%0], [%1], 16;"
                 :: "r"(dst), "l"(src));
}
#define CP_COMMIT() asm volatile("cp.async.commit_group;" ::: "memory")
#define CP_WAIT0()  asm volatile("cp.async.wait_group 0;" ::: "memory")

__device__ __forceinline__ void split_bf16(float v, __nv_bfloat16& hi, __nv_bfloat16& lo) {
    hi = __float2bfloat16(v);
    lo = __float2bfloat16(v - __bfloat162float(hi));
}

// GEMM smem
#define KPAD 72
#define TILE_B (128 * KPAD * 2)       // 18432 bytes
#define GEMM_SMEM (4 * TILE_B)        // 73728 bytes

// ---------------------------------------------------------------------------
// Conversion kernels
// ---------------------------------------------------------------------------
__global__ void conv_x(const float* __restrict__ x) {
    __shared__ float tile[32][33];
    const int b  = blockIdx.z;
    const int p0 = blockIdx.x * 32;
    const int c0 = blockIdx.y * 32;
    const int tx = threadIdx.x, ty = threadIdx.y;   // 32 x 8
    const float* xb = x + ((size_t)b * CCH + c0) * PIX + p0;
#pragma unroll
    for (int i = 0; i < 32; i += 8)
        tile[ty + i][tx] = xb[(size_t)(ty + i) * PIX + tx];
    __syncthreads();
#pragma unroll
    for (int i = 0; i < 32; i += 8) {
        int p = p0 + ty + i;
        float v = tile[tx][ty + i];
        __nv_bfloat16 hi, lo; split_bf16(v, hi, lo);
        size_t o = ((size_t)b * PIX + p) * CCH + c0 + tx;
        g_xh[o] = hi;
        g_xl[o] = lo;
    }
}

__global__ void conv_w(const float* __restrict__ w, __nv_bfloat16* __restrict__ wh,
                       __nv_bfloat16* __restrict__ wl, int n) {
    int i = blockIdx.x * 256 + threadIdx.x;
    if (i < n) {
        __nv_bfloat16 hi, lo; split_bf16(w[i], hi, lo);
        wh[i] = hi;
        wl[i] = lo;
    }
}

// ---------------------------------------------------------------------------
// Kernel 1: QKV projection (mma.sync bf16x3 + cp.async, 2 CTAs/SM).
// Identical to R8 (fp32 word stores in epilogue).
// ---------------------------------------------------------------------------
__global__ __launch_bounds__(256, 2) void qkv_mma(const float* __restrict__ b1) {
    extern __shared__ char smem[];
    char* sAh = smem;
    char* sAl = smem + TILE_B;
    char* sBh = smem + 2 * TILE_B;
    char* sBl = smem + 3 * TILE_B;
    const u32 uAh = smem_u32(sAh), uAl = smem_u32(sAl);
    const u32 uBh = smem_u32(sBh), uBl = smem_u32(sBl);

    const int tid = threadIdx.x;
    const int lane = tid & 31, wid = tid >> 5;
    const int warp_m = wid >> 1, warp_n = wid & 1;
    const int b  = blockIdx.z;
    const int p0 = blockIdx.x * 128;
    const int n0 = blockIdx.y * 128;

    const int g = lane >> 3, rr = lane & 7;
    const u32 offA = (u32)(((warp_m * 32 + rr + (g & 1) * 8) * KPAD + (g >> 1) * 8) * 2);
    const u32 offB = (u32)(((warp_n * 64 + (g >> 1) * 8 + rr) * KPAD + (g & 1) * 8) * 2);

    float acc[2][8][4];
#pragma unroll
    for (int ma = 0; ma < 2; ma++)
#pragma unroll
        for (int na = 0; na < 8; na++)
#pragma unroll
            for (int v = 0; v < 4; v++) acc[ma][na][v] = 0.f;

    const __nv_bfloat16* Ah = g_xh + (size_t)b * PIX * CCH;
    const __nv_bfloat16* Al = g_xl + (size_t)b * PIX * CCH;

    for (int c0 = 0; c0 < CCH; c0 += 64) {
#pragma unroll
        for (int t = 0; t < 4; t++) {
            int idx = tid + t * 256;
            int row = idx >> 3, seg = idx & 7;
            size_t srcA = ((size_t)(p0 + row)) * CCH + c0 + seg * 8;
            size_t srcB = ((size_t)(n0 + row)) * CCH + c0 + seg * 8;
            u32 doff = (u32)(row * (KPAD * 2) + seg * 16);
            cp16(uAh + doff, Ah + srcA);
            cp16(uAl + doff, Al + srcA);
            cp16(uBh + doff, g_w1h + srcB);
            cp16(uBl + doff, g_w1l + srcB);
        }
        CP_COMMIT();
        CP_WAIT0();
        __syncthreads();

#pragma unroll
        for (int ks = 0; ks < 4; ks++) {
            const u32 ko = ks * 32;
            u32 ah[2][4], al[2][4];
            ldsm4(ah[0], uAh + offA + ko);
            ldsm4(ah[1], uAh + offA + ko + 16 * KPAD * 2);
            ldsm4(al[0], uAl + offA + ko);
            ldsm4(al[1], uAl + offA + ko + 16 * KPAD * 2);
#pragma unroll
            for (int ng = 0; ng < 4; ng++) {
                u32 bh[4], bl[4];
                ldsm4(bh, uBh + offB + ko + ng * (16 * KPAD * 2));
                ldsm4(bl, uBl + offB + ko + ng * (16 * KPAD * 2));
#pragma unroll
                for (int h = 0; h < 2; h++) {
                    const u32* bhf = bh + 2 * h;
                    const u32* blf = bl + 2 * h;
                    int na = ng * 2 + h;
#pragma unroll
                    for (int ma = 0; ma < 2; ma++) {
                        mma_bf16(acc[ma][na], ah[ma], bhf);
                        mma_bf16(acc[ma][na], ah[ma], blf);
                        mma_bf16(acc[ma][na], al[ma], bhf);
                    }
                }
            }
        }
        __syncthreads();
    }

    // Epilogue: scatter fp32 into Q/K/V
    const int r = lane >> 2;
    const int cp = (lane & 3) * 2;
#pragma unroll
    for (int ma = 0; ma < 2; ma++) {
#pragma unroll
        for (int na = 0; na < 8; na++) {
#pragma unroll
            for (int v = 0; v < 4; v++) {
                int m  = p0 + warp_m * 32 + ma * 16 + r + (v >> 1) * 8;
                int oc = n0 + warp_n * 64 + na * 8 + cp + (v & 1);
                float val = acc[ma][na][v] + b1[oc];
                int type = oc % 3;
                int ch   = oc / 3;
                int head = ch >> 5;
                int e    = ch & 31;
                float* dst = (type == 0) ? g_Q : (type == 1) ? g_K : g_V;
                dst[((size_t)(b * NH + head) * PIX + m) * EDIM + e] = val;
            }
        }
    }
}

// ---------------------------------------------------------------------------
// Kernel 2: windowed attention via mma.sync bf16x3. One block (128 thr, 4
// warps) per (b, head, window). 144 keys = 9 k16-steps / 18 n8-atoms exactly.
// Warp-local after the load sync. P hi/lo overlays S rows. 90.6 KB smem.
// ---------------------------------------------------------------------------
#define AQ_K   40            // Q/K smem k-stride (elements); row = 80 B
#define AVT_S  152           // Vt key-stride (elements); row = 304 B (19x16)
#define SROW_B 592           // S row bytes (37x16 -> ldmatrix conflict-free)
#define PLO_B  304           // P_lo byte offset within S row (19x16)
// smem byte offsets
#define A_QH  0
#define A_QL  5120
#define A_KH  10240          // 144*40*2 = 11520
#define A_KL  21760
#define A_VTH 33280          // 32*152*2 = 9728
#define A_VTL 43008
#define A_S   52736          // 64 * 592 = 37888
#define ATTN_SMEM (A_S + 64 * SROW_B)   // 90624

__global__ __launch_bounds__(128, 2) void attn_mma() {
    extern __shared__ char sm[];
    const u32 sb = smem_u32(sm);

    const int b    = blockIdx.z;
    const int head = blockIdx.y;
    const int wi   = blockIdx.x >> 3;
    const int wj   = blockIdx.x & 7;
    const int tid  = threadIdx.x;
    const int lane = tid & 31;
    const int warp = tid >> 5;

    const size_t hb = (size_t)(b * NH + head) * PIX * EDIM;
    const float* Qg = g_Q + hb;
    const float* Kg = g_K + hb;
    const float* Vg = g_V + hb;

    // ---- Load Q (64x32), K (144x32), Vt (32x144); fp32 -> bf16 hi/lo
    for (int idx = tid; idx < 64 * EDIM; idx += 128) {
        int q = idx >> 5, e = idx & 31;
        int r = wi * 8 + (q >> 3);
        int c = wj * 8 + (q & 7);
        float v = Qg[(size_t)(r * WW + c) * EDIM + e];
        __nv_bfloat16 hi, lo; split_bf16(v, hi, lo);
        *(__nv_bfloat16*)(sm + A_QH + (q * AQ_K + e) * 2) = hi;
        *(__nv_bfloat16*)(sm + A_QL + (q * AQ_K + e) * 2) = lo;
    }
    for (int idx = tid; idx < NKEY * EDIM; idx += 128) {
        int k = idx >> 5, e = idx & 31;
        int kr = k / MO, kc = k % MO;
        int r = wi * 8 - 2 + kr;
        int c = wj * 8 - 2 + kc;
        float kv = 0.f, vv = 0.f;
        if (r >= 0 && r < HH && c >= 0 && c < WW) {
            size_t off = (size_t)(r * WW + c) * EDIM + e;
            kv = Kg[off];
            vv = Vg[off];
        }
        __nv_bfloat16 kh, kl, vh, vl;
        split_bf16(kv, kh, kl);
        split_bf16(vv, vh, vl);
        *(__nv_bfloat16*)(sm + A_KH + (k * AQ_K + e) * 2) = kh;
        *(__nv_bfloat16*)(sm + A_KL + (k * AQ_K + e) * 2) = kl;
        *(__nv_bfloat16*)(sm + A_VTH + (e * AVT_S + k) * 2) = vh;
        *(__nv_bfloat16*)(sm + A_VTL + (e * AVT_S + k) * 2) = vl;
    }
    __syncthreads();

    const int g = lane >> 3, rr = lane & 7;

    // ---- QK^T: warp m-atom (16 q) x 18 n-atoms (144 keys) x 2 ksteps
    {
        const u32 aoff = (u32)(((warp * 16 + rr + (g & 1) * 8) * AQ_K + (g >> 1) * 8) * 2);
        const u32 boff = (u32)((((g >> 1) * 8 + rr) * AQ_K + (g & 1) * 8) * 2);
        float acc[18][4];
#pragma unroll
        for (int na = 0; na < 18; na++)
#pragma unroll
            for (int v = 0; v < 4; v++) acc[na][v] = 0.f;

#pragma unroll
        for (int ks = 0; ks < 2; ks++) {
            const u32 ko = ks * 32;
            u32 ah[4], al[4];
            ldsm4(ah, sb + A_QH + aoff + ko);
            ldsm4(al, sb + A_QL + aoff + ko);
#pragma unroll
            for (int ng = 0; ng < 9; ng++) {
                u32 bh[4], bl[4];
                const u32 nb = ng * (16 * AQ_K * 2);
                ldsm4(bh, sb + A_KH + boff + nb + ko);
                ldsm4(bl, sb + A_KL + boff + nb + ko);
#pragma unroll
                for (int h = 0; h < 2; h++) {
                    int na = ng * 2 + h;
                    mma_bf16(acc[na], ah, bh + 2 * h);
                    mma_bf16(acc[na], ah, bl + 2 * h);
                    mma_bf16(acc[na], al, bh + 2 * h);
                }
            }
        }
        // store scaled scores to S fp32 (warp-owned rows)
        const float scale = 0.17677669529663687f;   // 1/sqrt(32)
        const int r0 = warp * 16 + (lane >> 2);
        const int c0 = (lane & 3) * 2;
#pragma unroll
        for (int na = 0; na < 18; na++) {
            int col = na * 8 + c0;
            *(float2*)(sm + A_S + (size_t)r0 * SROW_B + col * 4) =
                make_float2(acc[na][0] * scale, acc[na][1] * scale);
            *(float2*)(sm + A_S + (size_t)(r0 + 8) * SROW_B + col * 4) =
                make_float2(acc[na][2] * scale, acc[na][3] * scale);
        }
    }
    __syncwarp();

    // ---- softmax: warp-local, 4 threads/row x 36 cols, 2 passes of 8 rows.
    //      Reads staged in regs (36), shfl barriers order reads before the
    //      P hi/lo overlay writes into the same row bytes.
#pragma unroll
    for (int pass = 0; pass < 2; pass++) {
        const int row = warp * 16 + pass * 8 + (lane >> 2);
        const int seg = lane & 3;
        char* prow = sm + A_S + (size_t)row * SROW_B;
        const float* src = (const float*)prow + seg * 36;
        float v[36];
#pragma unroll
        for (int k = 0; k < 36; k++) v[k] = src[k];
        float m = -1e30f;
#pragma unroll
        for (int k = 0; k < 36; k++) m = fmaxf(m, v[k]);
        m = fmaxf(m, __shfl_xor_sync(0xFFFFFFFFu, m, 1));
        m = fmaxf(m, __shfl_xor_sync(0xFFFFFFFFu, m, 2));
        float s = 0.f;
#pragma unroll
        for (int k = 0; k < 36; k++) {
            v[k] = fast_exp(v[k] - m);
            s += v[k];
        }
        s += __shfl_xor_sync(0xFFFFFFFFu, s, 1);
        s += __shfl_xor_sync(0xFFFFFFFFu, s, 2);   // all reads done before this
        float inv = 1.f / s;
#pragma unroll
        for (int k = 0; k < 36; k++) {
            float p = v[k] * inv;
            __nv_bfloat16 hi, lo; split_bf16(p, hi, lo);
            int col = seg * 36 + k;
            *(__nv_bfloat16*)(prow + col * 2) = hi;
            *(__nv_bfloat16*)(prow + PLO_B + col * 2) = lo;
        }
    }
    __syncwarp();

    // ---- A@V: warp m-atom (16 q) x 4 n-atoms (32 e) x 9 ksteps
    {
        const u32 paoff = (u32)((warp * 16 + rr + (g & 1) * 8) * SROW_B + (g >> 1) * 16);
        const u32 vboff = (u32)((((g >> 1) * 8 + rr) * AVT_S + (g & 1) * 8) * 2);
        float acc[4][4];
#pragma unroll
        for (int na = 0; na < 4; na++)
#pragma unroll
            for (int v = 0; v < 4; v++) acc[na][v] = 0.f;

#pragma unroll
        for (int ks = 0; ks < 9; ks++) {
            const u32 ko = ks * 32;
            u32 ph[4], pl[4];
            ldsm4(ph, sb + A_S + paoff + ko);
            ldsm4(pl, sb + A_S + PLO_B + paoff + ko);
#pragma unroll
            for (int ng = 0; ng < 2; ng++) {
                u32 vh[4], vl[4];
                const u32 nb = ng * (16 * AVT_S * 2);
                ldsm4(vh, sb + A_VTH + vboff + nb + ko);
                ldsm4(vl, sb + A_VTL + vboff + nb + ko);
#pragma unroll
                for (int h = 0; h < 2; h++) {
                    int na = ng * 2 + h;
                    mma_bf16(acc[na], ph, vh + 2 * h);
                    mma_bf16(acc[na], ph, vl + 2 * h);
                    mma_bf16(acc[na], pl, vh + 2 * h);
                }
            }
        }
        // epilogue: write bf16 hi/lo to g_atth/g_attl (b, pixel, head*32+e)
        const int r0 = lane >> 2;
        const int e0 = (lane & 3) * 2;
#pragma unroll
        for (int half = 0; half < 2; half++) {
            int q = warp * 16 + r0 + half * 8;
            int r = wi * 8 + (q >> 3);
            int c = wj * 8 + (q & 7);
            size_t base = ((size_t)b * PIX + r * WW + c) * CCH + head * EDIM;
#pragma unroll
            for (int na = 0; na < 4; na++) {
                int e = na * 8 + e0;
                float o0 = acc[na][half * 2 + 0];
                float o1 = acc[na][half * 2 + 1];
                __nv_bfloat16 h0, l0, h1, l1;
                split_bf16(o0, h0, l0);
                split_bf16(o1, h1, l1);
                __nv_bfloat162 hh; hh.x = h0; hh.y = h1;
                __nv_bfloat162 ll; ll.x = l0; ll.y = l1;
                *(__nv_bfloat162*)(g_atth + base + e) = hh;
                *(__nv_bfloat162*)(g_attl + base + e) = ll;
            }
        }
    }
}

// ---------------------------------------------------------------------------
// Kernel 3: output projection (mma.sync bf16x3 + cp.async, 2 CTAs/SM).
// Identical to R8.
// ---------------------------------------------------------------------------
__global__ __launch_bounds__(256, 2) void proj_mma(const float* __restrict__ b2,
                                                   float* __restrict__ y) {
    extern __shared__ char smem[];
    char* sAh = smem;
    char* sAl = smem + TILE_B;
    char* sBh = smem + 2 * TILE_B;
    char* sBl = smem + 3 * TILE_B;
    const u32 uAh = smem_u32(sAh), uAl = smem_u32(sAl);
    const u32 uBh = smem_u32(sBh), uBl = smem_u32(sBl);

    const int tid = threadIdx.x;
    const int lane = tid & 31, wid = tid >> 5;
    const int warp_m = wid >> 1, warp_n = wid & 1;
    const int b  = blockIdx.z;
    const int p0 = blockIdx.x * 128;
    const int n0 = blockIdx.y * 128;

    const int g = lane >> 3, rr = lane & 7;
    const u32 offA = (u32)(((warp_m * 32 + rr + (g & 1) * 8) * KPAD + (g >> 1) * 8) * 2);
    const u32 offB = (u32)(((warp_n * 64 + (g >> 1) * 8 + rr) * KPAD + (g & 1) * 8) * 2);

    float acc[2][8][4];
#pragma unroll
    for (int ma = 0; ma < 2; ma++)
#pragma unroll
        for (int na = 0; na < 8; na++)
#pragma unroll
            for (int v = 0; v < 4; v++) acc[ma][na][v] = 0.f;

    const __nv_bfloat16* Ah = g_atth + (size_t)b * PIX * CCH;
    const __nv_bfloat16* Al = g_attl + (size_t)b * PIX * CCH;

    for (int c0 = 0; c0 < CCH; c0 += 64) {
#pragma unroll
        for (int t = 0; t < 4; t++) {
            int idx = tid + t * 256;
            int row = idx >> 3, seg = idx & 7;
            size_t srcA = ((size_t)(p0 + row)) * CCH + c0 + seg * 8;
            size_t srcB = ((size_t)(n0 + row)) * CCH + c0 + seg * 8;
            u32 doff = (u32)(row * (KPAD * 2) + seg * 16);
            cp16(uAh + doff, Ah + srcA);
            cp16(uAl + doff, Al + srcA);
            cp16(uBh + doff, g_w2h + srcB);
            cp16(uBl + doff, g_w2l + srcB);
        }
        CP_COMMIT();
        CP_WAIT0();
        __syncthreads();

#pragma unroll
        for (int ks = 0; ks < 4; ks++) {
            const u32 ko = ks * 32;
            u32 ah[2][4], al[2][4];
            ldsm4(ah[0], uAh + offA + ko);
            ldsm4(ah[1], uAh + offA + ko + 16 * KPAD * 2);
            ldsm4(al[0], uAl + offA + ko);
            ldsm4(al[1], uAl + offA + ko + 16 * KPAD * 2);
#pragma unroll
            for (int ng = 0; ng < 4; ng++) {
                u32 bh[4], bl[4];
                ldsm4(bh, uBh + offB + ko + ng * (16 * KPAD * 2));
                ldsm4(bl, uBl + offB + ko + ng * (16 * KPAD * 2));
#pragma unroll
                for (int h = 0; h < 2; h++) {
                    const u32* bhf = bh + 2 * h;
                    const u32* blf = bl + 2 * h;
                    int na = ng * 2 + h;
#pragma unroll
                    for (int ma = 0; ma < 2; ma++) {
                        mma_bf16(acc[ma][na], ah[ma], bhf);
                        mma_bf16(acc[ma][na], ah[ma], blf);
                        mma_bf16(acc[ma][na], al[ma], bhf);
                    }
                }
            }
        }
        __syncthreads();
    }

    // Epilogue: y[b][n][p]
    const int r = lane >> 2;
    const int cp = (lane & 3) * 2;
#pragma unroll
    for (int ma = 0; ma < 2; ma++) {
#pragma unroll
        for (int na = 0; na < 8; na++) {
#pragma unroll
            for (int v = 0; v < 4; v++) {
                int m = p0 + warp_m * 32 + ma * 16 + r + (v >> 1) * 8;
                int n = n0 + warp_n * 64 + na * 8 + cp + (v & 1);
                y[((size_t)(b * CCH + n)) * PIX + m] = acc[ma][na][v] + b2[n];
            }
        }
    }
}

// ---------------------------------------------------------------------------
extern "C" void kernel_launch(void* const* d_in, const int* in_sizes, int n_in,
                              void* d_out, int out_size) {
    const float* x  = (const float*)d_in[0];
    const float* W1 = (const float*)d_in[1];
    const float* b1 = (const float*)d_in[2];
    const float* W2 = (const float*)d_in[3];
    const float* b2 = (const float*)d_in[4];
    float* y = (float*)d_out;

    cudaFuncSetAttribute(attn_mma,
                         cudaFuncAttributeMaxDynamicSharedMemorySize, ATTN_SMEM);
    cudaFuncSetAttribute(qkv_mma,
                         cudaFuncAttributeMaxDynamicSharedMemorySize, GEMM_SMEM);
    cudaFuncSetAttribute(proj_mma,
                         cudaFuncAttributeMaxDynamicSharedMemorySize, GEMM_SMEM);

    __nv_bfloat16 *w1h, *w1l, *w2h, *w2l;
    cudaGetSymbolAddress((void**)&w1h, g_w1h);
    cudaGetSymbolAddress((void**)&w1l, g_w1l);
    cudaGetSymbolAddress((void**)&w2h, g_w2h);
    cudaGetSymbolAddress((void**)&w2l, g_w2l);

    // 0) fp32 -> bf16 hi/lo splits
    conv_x<<<dim3(PIX / 32, CCH / 32, BATCH), dim3(32, 8)>>>(x);
    conv_w<<<(768 * CCH + 255) / 256, 256>>>(W1, w1h, w1l, 768 * CCH);
    conv_w<<<(CCH * CCH + 255) / 256, 256>>>(W2, w2h, w2l, CCH * CCH);

    // 1) QKV: M=4096 (x128), N=768 (x128), per batch
    qkv_mma<<<dim3(PIX / 128, 768 / 128, BATCH), 256, GEMM_SMEM>>>(b1);

    // 2) Attention: (64 windows, 8 heads, 16 batches)
    attn_mma<<<dim3(NWIN * NWIN, NH, BATCH), 128, ATTN_SMEM>>>();

    // 3) Output projection: N=256 (x128)
    proj_mma<<<dim3(PIX / 128, CCH / 128, BATCH), 256, GEMM_SMEM>>>(b2, y);
}

// round 11
// speedup vs baseline: 2.2946x; 1.6400x over previous
#include <cuda_runtime.h>
#include <cuda_bf16.h>
#include <math.h>

#define NH    8
#define EDIM  32
#define WS    8
#define MO    12
#define NKEY  (MO*MO)      // 144
#define BATCH 16
#define CCH   256
#define HH    64
#define WW    64
#define PIX   (HH*WW)      // 4096
#define NWIN  8

typedef unsigned long long u64;
typedef unsigned int u32;

// Scratch buffers
__device__ float g_Q[BATCH * NH * PIX * EDIM];    // (b, head, pixel, e)
__device__ float g_K[BATCH * NH * PIX * EDIM];
__device__ float g_V[BATCH * NH * PIX * EDIM];

// bf16 hi/lo split scratch
__device__ __nv_bfloat16 g_xh[BATCH * PIX * CCH];   // x transposed: (b, p, c)
__device__ __nv_bfloat16 g_xl[BATCH * PIX * CCH];
__device__ __nv_bfloat16 g_w1h[768 * CCH];          // (n, k)
__device__ __nv_bfloat16 g_w1l[768 * CCH];
__device__ __nv_bfloat16 g_w2h[CCH * CCH];
__device__ __nv_bfloat16 g_w2l[CCH * CCH];
__device__ __nv_bfloat16 g_atth[BATCH * PIX * CCH]; // attn out hi (b, p, c)
__device__ __nv_bfloat16 g_attl[BATCH * PIX * CCH]; // attn out lo

// ---- fast exp on FMA pipe ----
__device__ __forceinline__ float fast_exp(float x) {
    float y = fmaxf(x * 1.4426950408889634f, -125.0f);
    float z = y + 12582912.0f;
    int   n = __float_as_int(z) - 0x4B400000;
    float f = y - (z - 12582912.0f);
    float p = 1.540353039338161e-4f;
    p = fmaf(p, f, 0.0013333558146428443f);
    p = fmaf(p, f, 0.009618129107628477f);
    p = fmaf(p, f, 0.05550410866482158f);
    p = fmaf(p, f, 0.2402265069591007f);
    p = fmaf(p, f, 0.6931471805599453f);
    p = fmaf(p, f, 1.0f);
    return p * __int_as_float((n + 127) << 23);
}

// ---- mma.sync helpers ----
__device__ __forceinline__ u32 smem_u32(const void* p) {
    u32 a; asm("{ .reg .u64 t; cvta.to.shared.u64 t, %1; cvt.u32.u64 %0, t; }"
               : "=r"(a) : "l"(p));
    return a;
}
__device__ __forceinline__ void ldsm4(u32* r, u32 addr) {
    asm volatile("ldmatrix.sync.aligned.m8n8.x4.shared.b16 {%0,%1,%2,%3}, [%4];"
                 : "=r"(r[0]), "=r"(r[1]), "=r"(r[2]), "=r"(r[3]) : "r"(addr));
}
__device__ __forceinline__ void ldsm4t(u32* r, u32 addr) {
    asm volatile("ldmatrix.sync.aligned.m8n8.x4.trans.shared.b16 {%0,%1,%2,%3}, [%4];"
                 : "=r"(r[0]), "=r"(r[1]), "=r"(r[2]), "=r"(r[3]) : "r"(addr));
}
__device__ __forceinline__ void mma_bf16(float* d, const u32* a, const u32* b) {
    asm volatile(
        "mma.sync.aligned.m16n8k16.row.col.f32.bf16.bf16.f32 "
        "{%0,%1,%2,%3}, {%4,%5,%6,%7}, {%8,%9}, {%0,%1,%2,%3};"
        : "+f"(d[0]), "+f"(d[1]), "+f"(d[2]), "+f"(d[3])
        : "r"(a[0]), "r"(a[1]), "r"(a[2]), "r"(a[3]), "r"(b[0]), "r"(b[1]));
}
__device__ __forceinline__ void cp16(u32 dst, const void* src) {
    asm volatile("cp.async.cg.shared.global [%0], [%1], 16;"
                 :: "r"(dst), "l"(src));
}
#define CP_COMMIT() asm volatile("cp.async.commit_group;" ::: "memory")
#define CP_WAIT0()  asm volatile("cp.async.wait_group 0;" ::: "memory")

__device__ __forceinline__ void split_bf16(float v, __nv_bfloat16& hi, __nv_bfloat16& lo) {
    hi = __float2bfloat16(v);
    lo = __float2bfloat16(v - __bfloat162float(hi));
}
// pack two fp32 -> bf16x2 register (lo in low half, hi in high half)
__device__ __forceinline__ u32 pkbf2(float lo, float hi) {
    u32 d; asm("cvt.rn.bf16x2.f32 %0, %1, %2;" : "=r"(d) : "f"(hi), "f"(lo));
    return d;
}
// split float4 into packed hi (2x u32) and lo (2x u32) bf16x2 words
__device__ __forceinline__ void split4(float4 v, uint2& hi, uint2& lo) {
    hi.x = pkbf2(v.x, v.y);
    hi.y = pkbf2(v.z, v.w);
    __nv_bfloat162 h0 = *(__nv_bfloat162*)&hi.x;
    __nv_bfloat162 h1 = *(__nv_bfloat162*)&hi.y;
    lo.x = pkbf2(v.x - __bfloat162float(h0.x), v.y - __bfloat162float(h0.y));
    lo.y = pkbf2(v.z - __bfloat162float(h1.x), v.w - __bfloat162float(h1.y));
}

// GEMM smem
#define KPAD 72
#define TILE_B (128 * KPAD * 2)       // 18432 bytes
#define GEMM_SMEM (4 * TILE_B)        // 73728 bytes

// ---------------------------------------------------------------------------
// Conversion kernels
// ---------------------------------------------------------------------------
__global__ void conv_x(const float* __restrict__ x) {
    __shared__ float tile[32][33];
    const int b  = blockIdx.z;
    const int p0 = blockIdx.x * 32;
    const int c0 = blockIdx.y * 32;
    const int tx = threadIdx.x, ty = threadIdx.y;   // 32 x 8
    const float* xb = x + ((size_t)b * CCH + c0) * PIX + p0;
#pragma unroll
    for (int i = 0; i < 32; i += 8)
        tile[ty + i][tx] = xb[(size_t)(ty + i) * PIX + tx];
    __syncthreads();
#pragma unroll
    for (int i = 0; i < 32; i += 8) {
        int p = p0 + ty + i;
        float v = tile[tx][ty + i];
        __nv_bfloat16 hi, lo; split_bf16(v, hi, lo);
        size_t o = ((size_t)b * PIX + p) * CCH + c0 + tx;
        g_xh[o] = hi;
        g_xl[o] = lo;
    }
}

__global__ void conv_w(const float* __restrict__ w, __nv_bfloat16* __restrict__ wh,
                       __nv_bfloat16* __restrict__ wl, int n) {
    int i = blockIdx.x * 256 + threadIdx.x;
    if (i < n) {
        __nv_bfloat16 hi, lo; split_bf16(w[i], hi, lo);
        wh[i] = hi;
        wl[i] = lo;
    }
}

// ---------------------------------------------------------------------------
// Kernel 1: QKV projection (mma.sync bf16x3 + cp.async, 2 CTAs/SM). R8-exact.
// ---------------------------------------------------------------------------
__global__ __launch_bounds__(256, 2) void qkv_mma(const float* __restrict__ b1) {
    extern __shared__ char smem[];
    char* sAh = smem;
    char* sAl = smem + TILE_B;
    char* sBh = smem + 2 * TILE_B;
    char* sBl = smem + 3 * TILE_B;
    const u32 uAh = smem_u32(sAh), uAl = smem_u32(sAl);
    const u32 uBh = smem_u32(sBh), uBl = smem_u32(sBl);

    const int tid = threadIdx.x;
    const int lane = tid & 31, wid = tid >> 5;
    const int warp_m = wid >> 1, warp_n = wid & 1;
    const int b  = blockIdx.z;
    const int p0 = blockIdx.x * 128;
    const int n0 = blockIdx.y * 128;

    const int g = lane >> 3, rr = lane & 7;
    const u32 offA = (u32)(((warp_m * 32 + rr + (g & 1) * 8) * KPAD + (g >> 1) * 8) * 2);
    const u32 offB = (u32)(((warp_n * 64 + (g >> 1) * 8 + rr) * KPAD + (g & 1) * 8) * 2);

    float acc[2][8][4];
#pragma unroll
    for (int ma = 0; ma < 2; ma++)
#pragma unroll
        for (int na = 0; na < 8; na++)
#pragma unroll
            for (int v = 0; v < 4; v++) acc[ma][na][v] = 0.f;

    const __nv_bfloat16* Ah = g_xh + (size_t)b * PIX * CCH;
    const __nv_bfloat16* Al = g_xl + (size_t)b * PIX * CCH;

    for (int c0 = 0; c0 < CCH; c0 += 64) {
#pragma unroll
        for (int t = 0; t < 4; t++) {
            int idx = tid + t * 256;
            int row = idx >> 3, seg = idx & 7;
            size_t srcA = ((size_t)(p0 + row)) * CCH + c0 + seg * 8;
            size_t srcB = ((size_t)(n0 + row)) * CCH + c0 + seg * 8;
            u32 doff = (u32)(row * (KPAD * 2) + seg * 16);
            cp16(uAh + doff, Ah + srcA);
            cp16(uAl + doff, Al + srcA);
            cp16(uBh + doff, g_w1h + srcB);
            cp16(uBl + doff, g_w1l + srcB);
        }
        CP_COMMIT();
        CP_WAIT0();
        __syncthreads();

#pragma unroll
        for (int ks = 0; ks < 4; ks++) {
            const u32 ko = ks * 32;
            u32 ah[2][4], al[2][4];
            ldsm4(ah[0], uAh + offA + ko);
            ldsm4(ah[1], uAh + offA + ko + 16 * KPAD * 2);
            ldsm4(al[0], uAl + offA + ko);
            ldsm4(al[1], uAl + offA + ko + 16 * KPAD * 2);
#pragma unroll
            for (int ng = 0; ng < 4; ng++) {
                u32 bh[4], bl[4];
                ldsm4(bh, uBh + offB + ko + ng * (16 * KPAD * 2));
                ldsm4(bl, uBl + offB + ko + ng * (16 * KPAD * 2));
#pragma unroll
                for (int h = 0; h < 2; h++) {
                    const u32* bhf = bh + 2 * h;
                    const u32* blf = bl + 2 * h;
                    int na = ng * 2 + h;
#pragma unroll
                    for (int ma = 0; ma < 2; ma++) {
                        mma_bf16(acc[ma][na], ah[ma], bhf);
                        mma_bf16(acc[ma][na], ah[ma], blf);
                        mma_bf16(acc[ma][na], al[ma], bhf);
                    }
                }
            }
        }
        __syncthreads();
    }

    // Epilogue: scatter fp32 into Q/K/V
    const int r = lane >> 2;
    const int cp = (lane & 3) * 2;
#pragma unroll
    for (int ma = 0; ma < 2; ma++) {
#pragma unroll
        for (int na = 0; na < 8; na++) {
#pragma unroll
            for (int v = 0; v < 4; v++) {
                int m  = p0 + warp_m * 32 + ma * 16 + r + (v >> 1) * 8;
                int oc = n0 + warp_n * 64 + na * 8 + cp + (v & 1);
                float val = acc[ma][na][v] + b1[oc];
                int type = oc % 3;
                int ch   = oc / 3;
                int head = ch >> 5;
                int e    = ch & 31;
                float* dst = (type == 0) ? g_Q : (type == 1) ? g_K : g_V;
                dst[((size_t)(b * NH + head) * PIX + m) * EDIM + e] = val;
            }
        }
    }
}

// ---------------------------------------------------------------------------
// Kernel 2: windowed attention, mma.sync bf16x3 with REGISTER-RESIDENT P.
// One block (128 thr, 4 warps) per (b, head, window). Warp w owns q rows
// 16w..16w+15 for everything. float4 gather loads; V in [key][e] layout
// consumed via ldmatrix.trans; fragment softmax with shfl; P repacked from
// C-fragments straight into A-fragments. Single __syncthreads after loads.
// ---------------------------------------------------------------------------
#define EPAD 40              // e-stride (elements); row = 80 B
// smem byte offsets
#define A_QH  0              // 64*80  = 5120
#define A_QL  5120
#define A_KH  10240          // 144*80 = 11520
#define A_KL  21760
#define A_VH  33280
#define A_VL  44800
#define ATTN_SMEM 56320

__global__ __launch_bounds__(128) void attn_mma() {
    extern __shared__ char sm[];
    const u32 sb = smem_u32(sm);

    const int b    = blockIdx.z;
    const int head = blockIdx.y;
    const int wi   = blockIdx.x >> 3;
    const int wj   = blockIdx.x & 7;
    const int tid  = threadIdx.x;
    const int lane = tid & 31;
    const int warp = tid >> 5;

    const size_t hb = (size_t)(b * NH + head) * PIX * EDIM;
    const float* Qg = g_Q + hb;
    const float* Kg = g_K + hb;
    const float* Vg = g_V + hb;
    const float scale = 0.17677669529663687f;   // 1/sqrt(32), folded into Q

    // ---- Load Q (64x32, x scale), K/V (144x32); float4 loads, 8B stores
    for (int idx = tid; idx < 64 * 8; idx += 128) {
        int q = idx >> 3, e4 = (idx & 7) * 4;
        int r = wi * 8 + (q >> 3);
        int c = wj * 8 + (q & 7);
        float4 v = *(const float4*)(Qg + (size_t)(r * WW + c) * EDIM + e4);
        v.x *= scale; v.y *= scale; v.z *= scale; v.w *= scale;
        uint2 hi, lo; split4(v, hi, lo);
        u32 doff = (u32)((q * EPAD + e4) * 2);
        *(uint2*)(sm + A_QH + doff) = hi;
        *(uint2*)(sm + A_QL + doff) = lo;
    }
    for (int idx = tid; idx < NKEY * 8; idx += 128) {
        int k = idx >> 3, e4 = (idx & 7) * 4;
        int kr = k / MO, kc = k % MO;
        int r = wi * 8 - 2 + kr;
        int c = wj * 8 - 2 + kc;
        float4 kv = make_float4(0.f, 0.f, 0.f, 0.f);
        float4 vv = kv;
        if (r >= 0 && r < HH && c >= 0 && c < WW) {
            size_t off = (size_t)(r * WW + c) * EDIM + e4;
            kv = *(const float4*)(Kg + off);
            vv = *(const float4*)(Vg + off);
        }
        uint2 khi, klo, vhi, vlo;
        split4(kv, khi, klo);
        split4(vv, vhi, vlo);
        u32 doff = (u32)((k * EPAD + e4) * 2);
        *(uint2*)(sm + A_KH + doff) = khi;
        *(uint2*)(sm + A_KL + doff) = klo;
        *(uint2*)(sm + A_VH + doff) = vhi;
        *(uint2*)(sm + A_VL + doff) = vlo;
    }
    __syncthreads();

    const int g = lane >> 3, rr = lane & 7;

    // ---- QK^T: warp m-atom (16 q) x 18 n-atoms (144 keys) x 2 ksteps
    float acc[18][4];
#pragma unroll
    for (int na = 0; na < 18; na++)
#pragma unroll
        for (int v = 0; v < 4; v++) acc[na][v] = 0.f;
    {
        const u32 aoff = (u32)(((warp * 16 + rr + (g & 1) * 8) * EPAD + (g >> 1) * 8) * 2);
        const u32 boff = (u32)((((g >> 1) * 8 + rr) * EPAD + (g & 1) * 8) * 2);
#pragma unroll
        for (int ks = 0; ks < 2; ks++) {
            const u32 ko = ks * 32;
            u32 ah[4], al[4];
            ldsm4(ah, sb + A_QH + aoff + ko);
            ldsm4(al, sb + A_QL + aoff + ko);
#pragma unroll
            for (int ng = 0; ng < 9; ng++) {
                u32 bh[4], bl[4];
                const u32 nb = ng * (16 * EPAD * 2);
                ldsm4(bh, sb + A_KH + boff + nb + ko);
                ldsm4(bl, sb + A_KL + boff + nb + ko);
#pragma unroll
                for (int h = 0; h < 2; h++) {
                    int na = ng * 2 + h;
                    mma_bf16(acc[na], ah, bh + 2 * h);
                    mma_bf16(acc[na], ah, bl + 2 * h);
                    mma_bf16(acc[na], al, bh + 2 * h);
                }
            }
        }
    }

    // ---- fragment softmax (rows r and r+8 live in this thread + 3 lane-mates)
    {
        float m0 = -1e30f, m1 = -1e30f;
#pragma unroll
        for (int na = 0; na < 18; na++) {
            m0 = fmaxf(m0, fmaxf(acc[na][0], acc[na][1]));
            m1 = fmaxf(m1, fmaxf(acc[na][2], acc[na][3]));
        }
        m0 = fmaxf(m0, __shfl_xor_sync(0xFFFFFFFFu, m0, 1));
        m0 = fmaxf(m0, __shfl_xor_sync(0xFFFFFFFFu, m0, 2));
        m1 = fmaxf(m1, __shfl_xor_sync(0xFFFFFFFFu, m1, 1));
        m1 = fmaxf(m1, __shfl_xor_sync(0xFFFFFFFFu, m1, 2));
        float s0 = 0.f, s1 = 0.f;
#pragma unroll
        for (int na = 0; na < 18; na++) {
            acc[na][0] = fast_exp(acc[na][0] - m0);
            acc[na][1] = fast_exp(acc[na][1] - m0);
            acc[na][2] = fast_exp(acc[na][2] - m1);
            acc[na][3] = fast_exp(acc[na][3] - m1);
            s0 += acc[na][0] + acc[na][1];
            s1 += acc[na][2] + acc[na][3];
        }
        s0 += __shfl_xor_sync(0xFFFFFFFFu, s0, 1);
        s0 += __shfl_xor_sync(0xFFFFFFFFu, s0, 2);
        s1 += __shfl_xor_sync(0xFFFFFFFFu, s1, 1);
        s1 += __shfl_xor_sync(0xFFFFFFFFu, s1, 2);
        float i0 = 1.f / s0, i1 = 1.f / s1;
#pragma unroll
        for (int na = 0; na < 18; na++) {
            acc[na][0] *= i0;
            acc[na][1] *= i0;
            acc[na][2] *= i1;
            acc[na][3] *= i1;
        }
    }

    // ---- A@V: P packed from registers; V via ldmatrix.trans from [key][e]
    {
        float av[4][4];
#pragma unroll
        for (int na = 0; na < 4; na++)
#pragma unroll
            for (int v = 0; v < 4; v++) av[na][v] = 0.f;

        // trans ldmatrix address: row = ks*16 + (g&1)*8 + rr (key),
        // col = (g>>1)*8 + e0 (e)
        const u32 vrow = (u32)(((g & 1) * 8 + rr) * EPAD + (g >> 1) * 8);
#pragma unroll
        for (int ks = 0; ks < 9; ks++) {
            // P A-fragments for this kstep from C-fragments of atoms 2ks, 2ks+1
            u32 ph[4], pl[4];
            {
                float c00 = acc[2 * ks][0],     c01 = acc[2 * ks][1];
                float c02 = acc[2 * ks][2],     c03 = acc[2 * ks][3];
                float c10 = acc[2 * ks + 1][0], c11 = acc[2 * ks + 1][1];
                float c12 = acc[2 * ks + 1][2], c13 = acc[2 * ks + 1][3];
                ph[0] = pkbf2(c00, c01);
                ph[1] = pkbf2(c02, c03);
                ph[2] = pkbf2(c10, c11);
                ph[3] = pkbf2(c12, c13);
                __nv_bfloat162 h0 = *(__nv_bfloat162*)&ph[0];
                __nv_bfloat162 h1 = *(__nv_bfloat162*)&ph[1];
                __nv_bfloat162 h2 = *(__nv_bfloat162*)&ph[2];
                __nv_bfloat162 h3 = *(__nv_bfloat162*)&ph[3];
                pl[0] = pkbf2(c00 - __bfloat162float(h0.x), c01 - __bfloat162float(h0.y));
                pl[1] = pkbf2(c02 - __bfloat162float(h1.x), c03 - __bfloat162float(h1.y));
                pl[2] = pkbf2(c10 - __bfloat162float(h2.x), c11 - __bfloat162float(h2.y));
                pl[3] = pkbf2(c12 - __bfloat162float(h3.x), c13 - __bfloat162float(h3.y));
            }
            const u32 kb = (u32)(ks * 16 * EPAD * 2);
            // e0 = 0 -> e-atoms 0,1 ; e0 = 16 -> e-atoms 2,3
#pragma unroll
            for (int half = 0; half < 2; half++) {
                u32 vh[4], vl[4];
                const u32 addr = kb + (vrow + half * 16) * 2;
                ldsm4t(vh, sb + A_VH + addr);
                ldsm4t(vl, sb + A_VL + addr);
#pragma unroll
                for (int h = 0; h < 2; h++) {
                    int na = half * 2 + h;
                    mma_bf16(av[na], ph, vh + 2 * h);
                    mma_bf16(av[na], ph, vl + 2 * h);
                    mma_bf16(av[na], pl, vh + 2 * h);
                }
            }
        }

        // epilogue: write bf16 hi/lo to g_atth/g_attl (b, pixel, head*32+e)
        const int r0 = lane >> 2;
        const int e0 = (lane & 3) * 2;
#pragma unroll
        for (int half = 0; half < 2; half++) {
            int q = warp * 16 + r0 + half * 8;
            int r = wi * 8 + (q >> 3);
            int c = wj * 8 + (q & 7);
            size_t base = ((size_t)b * PIX + r * WW + c) * CCH + head * EDIM;
#pragma unroll
            for (int na = 0; na < 4; na++) {
                int e = na * 8 + e0;
                float o0 = av[na][half * 2 + 0];
                float o1 = av[na][half * 2 + 1];
                u32 hh = pkbf2(o0, o1);
                __nv_bfloat162 hv = *(__nv_bfloat162*)&hh;
                u32 ll = pkbf2(o0 - __bfloat162float(hv.x),
                               o1 - __bfloat162float(hv.y));
                *(u32*)((char*)(g_atth + base + e)) = hh;
                *(u32*)((char*)(g_attl + base + e)) = ll;
            }
        }
    }
}

// ---------------------------------------------------------------------------
// Kernel 3: output projection (mma.sync bf16x3 + cp.async, 2 CTAs/SM). R8-exact.
// ---------------------------------------------------------------------------
__global__ __launch_bounds__(256, 2) void proj_mma(const float* __restrict__ b2,
                                                   float* __restrict__ y) {
    extern __shared__ char smem[];
    char* sAh = smem;
    char* sAl = smem + TILE_B;
    char* sBh = smem + 2 * TILE_B;
    char* sBl = smem + 3 * TILE_B;
    const u32 uAh = smem_u32(sAh), uAl = smem_u32(sAl);
    const u32 uBh = smem_u32(sBh), uBl = smem_u32(sBl);

    const int tid = threadIdx.x;
    const int lane = tid & 31, wid = tid >> 5;
    const int warp_m = wid >> 1, warp_n = wid & 1;
    const int b  = blockIdx.z;
    const int p0 = blockIdx.x * 128;
    const int n0 = blockIdx.y * 128;

    const int g = lane >> 3, rr = lane & 7;
    const u32 offA = (u32)(((warp_m * 32 + rr + (g & 1) * 8) * KPAD + (g >> 1) * 8) * 2);
    const u32 offB = (u32)(((warp_n * 64 + (g >> 1) * 8 + rr) * KPAD + (g & 1) * 8) * 2);

    float acc[2][8][4];
#pragma unroll
    for (int ma = 0; ma < 2; ma++)
#pragma unroll
        for (int na = 0; na < 8; na++)
#pragma unroll
            for (int v = 0; v < 4; v++) acc[ma][na][v] = 0.f;

    const __nv_bfloat16* Ah = g_atth + (size_t)b * PIX * CCH;
    const __nv_bfloat16* Al = g_attl + (size_t)b * PIX * CCH;

    for (int c0 = 0; c0 < CCH; c0 += 64) {
#pragma unroll
        for (int t = 0; t < 4; t++) {
            int idx = tid + t * 256;
            int row = idx >> 3, seg = idx & 7;
            size_t srcA = ((size_t)(p0 + row)) * CCH + c0 + seg * 8;
            size_t srcB = ((size_t)(n0 + row)) * CCH + c0 + seg * 8;
            u32 doff = (u32)(row * (KPAD * 2) + seg * 16);
            cp16(uAh + doff, Ah + srcA);
            cp16(uAl + doff, Al + srcA);
            cp16(uBh + doff, g_w2h + srcB);
            cp16(uBl + doff, g_w2l + srcB);
        }
        CP_COMMIT();
        CP_WAIT0();
        __syncthreads();

#pragma unroll
        for (int ks = 0; ks < 4; ks++) {
            const u32 ko = ks * 32;
            u32 ah[2][4], al[2][4];
            ldsm4(ah[0], uAh + offA + ko);
            ldsm4(ah[1], uAh + offA + ko + 16 * KPAD * 2);
            ldsm4(al[0], uAl + offA + ko);
            ldsm4(al[1], uAl + offA + ko + 16 * KPAD * 2);
#pragma unroll
            for (int ng = 0; ng < 4; ng++) {
                u32 bh[4], bl[4];
                ldsm4(bh, uBh + offB + ko + ng * (16 * KPAD * 2));
                ldsm4(bl, uBl + offB + ko + ng * (16 * KPAD * 2));
#pragma unroll
                for (int h = 0; h < 2; h++) {
                    const u32* bhf = bh + 2 * h;
                    const u32* blf = bl + 2 * h;
                    int na = ng * 2 + h;
#pragma unroll
                    for (int ma = 0; ma < 2; ma++) {
                        mma_bf16(acc[ma][na], ah[ma], bhf);
                        mma_bf16(acc[ma][na], ah[ma], blf);
                        mma_bf16(acc[ma][na], al[ma], bhf);
                    }
                }
            }
        }
        __syncthreads();
    }

    // Epilogue: y[b][n][p]
    const int r = lane >> 2;
    const int cp = (lane & 3) * 2;
#pragma unroll
    for (int ma = 0; ma < 2; ma++) {
#pragma unroll
        for (int na = 0; na < 8; na++) {
#pragma unroll
            for (int v = 0; v < 4; v++) {
                int m = p0 + warp_m * 32 + ma * 16 + r + (v >> 1) * 8;
                int n = n0 + warp_n * 64 + na * 8 + cp + (v & 1);
                y[((size_t)(b * CCH + n)) * PIX + m] = acc[ma][na][v] + b2[n];
            }
        }
    }
}

// ---------------------------------------------------------------------------
extern "C" void kernel_launch(void* const* d_in, const int* in_sizes, int n_in,
                              void* d_out, int out_size) {
    const float* x  = (const float*)d_in[0];
    const float* W1 = (const float*)d_in[1];
    const float* b1 = (const float*)d_in[2];
    const float* W2 = (const float*)d_in[3];
    const float* b2 = (const float*)d_in[4];
    float* y = (float*)d_out;

    cudaFuncSetAttribute(attn_mma,
                         cudaFuncAttributeMaxDynamicSharedMemorySize, ATTN_SMEM);
    cudaFuncSetAttribute(qkv_mma,
                         cudaFuncAttributeMaxDynamicSharedMemorySize, GEMM_SMEM);
    cudaFuncSetAttribute(proj_mma,
                         cudaFuncAttributeMaxDynamicSharedMemorySize, GEMM_SMEM);

    __nv_bfloat16 *w1h, *w1l, *w2h, *w2l;
    cudaGetSymbolAddress((void**)&w1h, g_w1h);
    cudaGetSymbolAddress((void**)&w1l, g_w1l);
    cudaGetSymbolAddress((void**)&w2h, g_w2h);
    cudaGetSymbolAddress((void**)&w2l, g_w2l);

    // 0) fp32 -> bf16 hi/lo splits
    conv_x<<<dim3(PIX / 32, CCH / 32, BATCH), dim3(32, 8)>>>(x);
    conv_w<<<(768 * CCH + 255) / 256, 256>>>(W1, w1h, w1l, 768 * CCH);
    conv_w<<<(CCH * CCH + 255) / 256, 256>>>(W2, w2h, w2l, CCH * CCH);

    // 1) QKV: M=4096 (x128), N=768 (x128), per batch
    qkv_mma<<<dim3(PIX / 128, 768 / 128, BATCH), 256, GEMM_SMEM>>>(b1);

    // 2) Attention: (64 windows, 8 heads, 16 batches)
    attn_mma<<<dim3(NWIN * NWIN, NH, BATCH), 128, ATTN_SMEM>>>();

    // 3) Output projection: N=256 (x128)
    proj_mma<<<dim3(PIX / 128, CCH / 128, BATCH), 256, GEMM_SMEM>>>(b2, y);
}